// round 1
// baseline (speedup 1.0000x reference)
#include <cuda_runtime.h>

// ---------------- problem constants ----------------
constexpr int BATCH = 2;
constexpr int NSEQ  = 2048;
constexpr int DM    = 1024;
constexpr int NH    = 16;
constexpr int DH    = 64;
constexpr int MROWS = BATCH * NSEQ;   // 4096

// ---------------- scratch (static device globals; no allocation) ----------------
__device__ float g_q[BATCH * NH * NSEQ * DH];     // 16 MB
__device__ float g_k[BATCH * NH * NSEQ * DH];     // 16 MB
__device__ float g_v[BATCH * NH * NSEQ * DH];     // 16 MB
__device__ float g_att[MROWS * DM];               // 16 MB

// =====================================================================
// Kernel 1: QKV GEMM  y = x @ w_qkv, scatter into q/k/v [b,h,n,d]
//   x: [4096, 1024], w_qkv: [1024, 3072]
//   column c -> which = c%3, hd = c/3, h = hd>>6, d = hd&63
// 128x128x8 tile, 256 threads, 8x8 per-thread micro-tile.
// =====================================================================
__global__ __launch_bounds__(256) void qkv_gemm(const float* __restrict__ A,
                                                const float* __restrict__ Bw)
{
    constexpr int K = DM;        // 1024
    constexpr int N = 3 * DM;    // 3072
    __shared__ float As[8][128];
    __shared__ float Bs[8][128];

    const int bx = blockIdx.x;   // 0..23
    const int by = blockIdx.y;   // 0..31
    const int tid = threadIdx.x;
    const int tx = tid & 15;
    const int ty = tid >> 4;

    const int arow = tid >> 1;           // 0..127
    const int acol = (tid & 1) * 4;      // 0 or 4
    const int brow = tid >> 5;           // 0..7
    const int bcol = (tid & 31) * 4;     // 0..124

    const float* Ab = A + (size_t)by * 128 * K;
    const float* Bb = Bw + bx * 128;

    float acc[8][8] = {};

    for (int k0 = 0; k0 < K; k0 += 8) {
        float4 a4 = *(const float4*)(Ab + (size_t)arow * K + k0 + acol);
        As[acol + 0][arow] = a4.x;
        As[acol + 1][arow] = a4.y;
        As[acol + 2][arow] = a4.z;
        As[acol + 3][arow] = a4.w;
        *(float4*)&Bs[brow][bcol] = *(const float4*)(Bb + (size_t)(k0 + brow) * N + bcol);
        __syncthreads();
        #pragma unroll
        for (int kk = 0; kk < 8; kk++) {
            float rm[8], rn[8];
            #pragma unroll
            for (int i = 0; i < 8; i++) rm[i] = As[kk][ty * 8 + i];
            #pragma unroll
            for (int j = 0; j < 8; j++) rn[j] = Bs[kk][tx * 8 + j];
            #pragma unroll
            for (int i = 0; i < 8; i++)
                #pragma unroll
                for (int j = 0; j < 8; j++)
                    acc[i][j] = fmaf(rm[i], rn[j], acc[i][j]);
        }
        __syncthreads();
    }

    #pragma unroll
    for (int i = 0; i < 8; i++) {
        const int m = by * 128 + ty * 8 + i;
        const int bb = m >> 11;         // /2048
        const int n  = m & 2047;
        #pragma unroll
        for (int j = 0; j < 8; j++) {
            const int c = bx * 128 + tx * 8 + j;
            const int which = c % 3;
            const int hd = c / 3;
            const int h = hd >> 6;
            const int d = hd & 63;
            const size_t o = ((((size_t)bb * NH + h) * NSEQ + n) << 6) + d;
            const float val = acc[i][j];
            if (which == 0)      g_q[o] = val;
            else if (which == 1) g_k[o] = val;
            else                 g_v[o] = val;
        }
    }
}

// =====================================================================
// Kernel 2: causal flash attention (fp32, online softmax)
//   block = (q-tile of 64 rows) x (one b,h).  Key tiles of 32.
//   256 threads as 16x16:  S phase rows ty*4+i, cols tx*2+j
//                          PV phase rows ty*4+i, d-cols tx*4+j
// =====================================================================
__global__ __launch_bounds__(256) void attn_kernel()
{
    const int qt = gridDim.x - 1 - blockIdx.x;   // big tiles first (causal tail)
    const int bh = blockIdx.y;                   // 0..31
    const float* Qb = g_q + (size_t)bh * NSEQ * DH;
    const float* Kb = g_k + (size_t)bh * NSEQ * DH;
    const float* Vb = g_v + (size_t)bh * NSEQ * DH;
    const int bb = bh >> 4;
    const int hh = bh & 15;

    __shared__ float Qs[64][65];
    __shared__ float Ks[32][65];
    __shared__ float Vs[32][65];
    __shared__ float Ps[64][33];

    const int tid = threadIdx.x;
    const int tx = tid & 15;
    const int ty = tid >> 4;

    // load Q tile (64 x 64)
    {
        const int r0 = tid >> 4;            // 0..15
        const int cc = (tid & 15) * 4;      // 0..60
        #pragma unroll
        for (int rr = 0; rr < 64; rr += 16) {
            float4 v4 = *(const float4*)(Qb + (size_t)(qt * 64 + r0 + rr) * DH + cc);
            Qs[r0 + rr][cc + 0] = v4.x;
            Qs[r0 + rr][cc + 1] = v4.y;
            Qs[r0 + rr][cc + 2] = v4.z;
            Qs[r0 + rr][cc + 3] = v4.w;
        }
    }

    float o[4][4] = {};
    float mrow[4], lrow[4];
    #pragma unroll
    for (int i = 0; i < 4; i++) { mrow[i] = -1e30f; lrow[i] = 0.f; }

    const int ntiles = qt * 2 + 2;
    for (int kt = 0; kt < ntiles; kt++) {
        __syncthreads();   // previous iter's Ps/Vs readers done before overwrite
        {
            const int r0 = tid >> 4;
            const int cc = (tid & 15) * 4;
            #pragma unroll
            for (int rr = 0; rr < 32; rr += 16) {
                float4 k4 = *(const float4*)(Kb + (size_t)(kt * 32 + r0 + rr) * DH + cc);
                Ks[r0 + rr][cc + 0] = k4.x; Ks[r0 + rr][cc + 1] = k4.y;
                Ks[r0 + rr][cc + 2] = k4.z; Ks[r0 + rr][cc + 3] = k4.w;
                float4 v4 = *(const float4*)(Vb + (size_t)(kt * 32 + r0 + rr) * DH + cc);
                Vs[r0 + rr][cc + 0] = v4.x; Vs[r0 + rr][cc + 1] = v4.y;
                Vs[r0 + rr][cc + 2] = v4.z; Vs[r0 + rr][cc + 3] = v4.w;
            }
        }
        __syncthreads();

        // S = Q K^T
        float s[4][2] = {};
        #pragma unroll 8
        for (int kk = 0; kk < 64; kk++) {
            const float q0 = Qs[ty * 4 + 0][kk];
            const float q1 = Qs[ty * 4 + 1][kk];
            const float q2 = Qs[ty * 4 + 2][kk];
            const float q3 = Qs[ty * 4 + 3][kk];
            const float k0 = Ks[tx * 2 + 0][kk];
            const float k1 = Ks[tx * 2 + 1][kk];
            s[0][0] = fmaf(q0, k0, s[0][0]); s[0][1] = fmaf(q0, k1, s[0][1]);
            s[1][0] = fmaf(q1, k0, s[1][0]); s[1][1] = fmaf(q1, k1, s[1][1]);
            s[2][0] = fmaf(q2, k0, s[2][0]); s[2][1] = fmaf(q2, k1, s[2][1]);
            s[3][0] = fmaf(q3, k0, s[3][0]); s[3][1] = fmaf(q3, k1, s[3][1]);
        }

        const bool need_mask = (kt >= 2 * qt);

        #pragma unroll
        for (int i = 0; i < 4; i++) {
            const int grow = qt * 64 + ty * 4 + i;
            float sv[2];
            float tm = -1e30f;
            #pragma unroll
            for (int j = 0; j < 2; j++) {
                float v = s[i][j] * 0.125f;   // 1/sqrt(64)
                if (need_mask && (kt * 32 + tx * 2 + j > grow)) v = -1e30f;
                sv[j] = v;
                tm = fmaxf(tm, v);
            }
            #pragma unroll
            for (int off = 8; off > 0; off >>= 1)
                tm = fmaxf(tm, __shfl_xor_sync(0xffffffffu, tm, off));
            const float mnew = fmaxf(mrow[i], tm);
            const float f = __expf(mrow[i] - mnew);
            mrow[i] = mnew;
            float rs = 0.f;
            #pragma unroll
            for (int j = 0; j < 2; j++) {
                const float p = __expf(sv[j] - mnew);
                Ps[ty * 4 + i][tx * 2 + j] = p;
                rs += p;
            }
            #pragma unroll
            for (int off = 8; off > 0; off >>= 1)
                rs += __shfl_xor_sync(0xffffffffu, rs, off);
            lrow[i] = lrow[i] * f + rs;
            #pragma unroll
            for (int j = 0; j < 4; j++) o[i][j] *= f;
        }
        __syncthreads();

        // O += P @ V   (d-cols tx*4+j)
        #pragma unroll 4
        for (int kk = 0; kk < 32; kk++) {
            const float p0 = Ps[ty * 4 + 0][kk];
            const float p1 = Ps[ty * 4 + 1][kk];
            const float p2 = Ps[ty * 4 + 2][kk];
            const float p3 = Ps[ty * 4 + 3][kk];
            const float v0 = Vs[kk][tx * 4 + 0];
            const float v1 = Vs[kk][tx * 4 + 1];
            const float v2 = Vs[kk][tx * 4 + 2];
            const float v3 = Vs[kk][tx * 4 + 3];
            o[0][0] = fmaf(p0, v0, o[0][0]); o[0][1] = fmaf(p0, v1, o[0][1]);
            o[0][2] = fmaf(p0, v2, o[0][2]); o[0][3] = fmaf(p0, v3, o[0][3]);
            o[1][0] = fmaf(p1, v0, o[1][0]); o[1][1] = fmaf(p1, v1, o[1][1]);
            o[1][2] = fmaf(p1, v2, o[1][2]); o[1][3] = fmaf(p1, v3, o[1][3]);
            o[2][0] = fmaf(p2, v0, o[2][0]); o[2][1] = fmaf(p2, v1, o[2][1]);
            o[2][2] = fmaf(p2, v2, o[2][2]); o[2][3] = fmaf(p2, v3, o[2][3]);
            o[3][0] = fmaf(p3, v0, o[3][0]); o[3][1] = fmaf(p3, v1, o[3][1]);
            o[3][2] = fmaf(p3, v2, o[3][2]); o[3][3] = fmaf(p3, v3, o[3][3]);
        }
    }

    // normalize + store to [b, n, h*64 + d]
    #pragma unroll
    for (int i = 0; i < 4; i++) {
        const float inv = 1.f / lrow[i];
        const int n = qt * 64 + ty * 4 + i;
        const size_t base = ((size_t)bb * NSEQ + n) * DM + hh * 64 + tx * 4;
        #pragma unroll
        for (int j = 0; j < 4; j++)
            g_att[base + j] = o[i][j] * inv;
    }
}

// =====================================================================
// Kernel 3: output projection  out = g_att @ w_proj
//   [4096, 1024] x [1024, 1024]
// =====================================================================
__global__ __launch_bounds__(256) void proj_gemm(const float* __restrict__ Bw,
                                                 float* __restrict__ C)
{
    constexpr int K = DM;   // 1024
    constexpr int N = DM;   // 1024
    __shared__ float As[8][128];
    __shared__ float Bs[8][128];

    const int bx = blockIdx.x;   // 0..7
    const int by = blockIdx.y;   // 0..31
    const int tid = threadIdx.x;
    const int tx = tid & 15;
    const int ty = tid >> 4;

    const int arow = tid >> 1;
    const int acol = (tid & 1) * 4;
    const int brow = tid >> 5;
    const int bcol = (tid & 31) * 4;

    const float* Ab = g_att + (size_t)by * 128 * K;
    const float* Bb = Bw + bx * 128;

    float acc[8][8] = {};

    for (int k0 = 0; k0 < K; k0 += 8) {
        float4 a4 = *(const float4*)(Ab + (size_t)arow * K + k0 + acol);
        As[acol + 0][arow] = a4.x;
        As[acol + 1][arow] = a4.y;
        As[acol + 2][arow] = a4.z;
        As[acol + 3][arow] = a4.w;
        *(float4*)&Bs[brow][bcol] = *(const float4*)(Bb + (size_t)(k0 + brow) * N + bcol);
        __syncthreads();
        #pragma unroll
        for (int kk = 0; kk < 8; kk++) {
            float rm[8], rn[8];
            #pragma unroll
            for (int i = 0; i < 8; i++) rm[i] = As[kk][ty * 8 + i];
            #pragma unroll
            for (int j = 0; j < 8; j++) rn[j] = Bs[kk][tx * 8 + j];
            #pragma unroll
            for (int i = 0; i < 8; i++)
                #pragma unroll
                for (int j = 0; j < 8; j++)
                    acc[i][j] = fmaf(rm[i], rn[j], acc[i][j]);
        }
        __syncthreads();
    }

    #pragma unroll
    for (int i = 0; i < 8; i++) {
        const int m = by * 128 + ty * 8 + i;
        float* cp = C + (size_t)m * N + bx * 128 + tx * 8;
        float4 s0 = make_float4(acc[i][0], acc[i][1], acc[i][2], acc[i][3]);
        float4 s1 = make_float4(acc[i][4], acc[i][5], acc[i][6], acc[i][7]);
        *(float4*)(cp + 0) = s0;
        *(float4*)(cp + 4) = s1;
    }
}

// =====================================================================
extern "C" void kernel_launch(void* const* d_in, const int* in_sizes, int n_in,
                              void* d_out, int out_size)
{
    (void)in_sizes; (void)n_in; (void)out_size;
    const float* x      = (const float*)d_in[0];
    const float* w_qkv  = (const float*)d_in[1];
    const float* w_proj = (const float*)d_in[2];
    float* out = (float*)d_out;

    qkv_gemm<<<dim3(24, 32), 256>>>(x, w_qkv);   // 3072/128 x 4096/128
    attn_kernel<<<dim3(32, 32), 256>>>();        // 32 q-tiles x 32 (b,h)
    proj_gemm<<<dim3(8, 32), 256>>>(w_proj, out);
}

// round 2
// speedup vs baseline: 1.2757x; 1.2757x over previous
#include <cuda_runtime.h>

// ---------------- problem constants ----------------
constexpr int BATCH = 2;
constexpr int NSEQ  = 2048;
constexpr int DM    = 1024;
constexpr int NH    = 16;
constexpr int DH    = 64;

// ---------------- scratch (static device globals; no allocation) ----------------
// q, k stored TRANSPOSED per head: [b,h,d,n]  (so attention loads need no transpose)
// v stored [b,h,n,d]
__device__ float g_q[BATCH * NH * DH * NSEQ];
__device__ float g_k[BATCH * NH * DH * NSEQ];
__device__ float g_v[BATCH * NH * NSEQ * DH];
__device__ float g_att[BATCH * NSEQ * DM];

// =====================================================================
// Double-buffered 128x128x16 SGEMM core (256 threads, 8x8 micro-tile)
// =====================================================================

// Kernel 1: QKV GEMM  y = x @ w_qkv, scatter into q/k/v.
// column c -> which = c%3, hd = c/3, h = hd>>6, d = hd&63
__global__ __launch_bounds__(256, 2) void qkv_gemm(const float* __restrict__ A,
                                                   const float* __restrict__ Bw)
{
    constexpr int K = DM;        // 1024
    constexpr int N = 3 * DM;    // 3072
    __shared__ __align__(16) float As[2][16][132];   // [k][m], padded
    __shared__ __align__(16) float Bs[2][16][128];   // [k][n]

    const int bx = blockIdx.x;
    const int by = blockIdx.y;
    const int tid = threadIdx.x;
    const int tx = tid & 15;
    const int ty = tid >> 4;

    const float* Ab = A + (size_t)by * 128 * K;
    const float* Bb = Bw + bx * 128;

    // load indices
    const int a_row = tid >> 2;          // 0..63 (x4 over r)
    const int a_c4  = tid & 3;           // float4 col within 16-k
    const int b_row = tid >> 5;          // 0..7  (x2 over r)
    const int b_c4  = tid & 31;

    float4 ra[2], rb[2];
    float acc[8][8] = {};

    // preload tile 0
    #pragma unroll
    for (int r = 0; r < 2; r++) {
        ra[r] = *(const float4*)(Ab + (size_t)(a_row + 64 * r) * K + a_c4 * 4);
        rb[r] = *(const float4*)(Bb + (size_t)(b_row + 8 * r) * N + b_c4 * 4);
    }
    int buf = 0;
    #pragma unroll
    for (int r = 0; r < 2; r++) {
        const int ar = a_row + 64 * r;
        As[buf][a_c4 * 4 + 0][ar] = ra[r].x;
        As[buf][a_c4 * 4 + 1][ar] = ra[r].y;
        As[buf][a_c4 * 4 + 2][ar] = ra[r].z;
        As[buf][a_c4 * 4 + 3][ar] = ra[r].w;
        *(float4*)&Bs[buf][b_row + 8 * r][b_c4 * 4] = rb[r];
    }
    __syncthreads();

    for (int k0 = 0; k0 < K; k0 += 16) {
        const bool more = (k0 + 16 < K);
        if (more) {
            #pragma unroll
            for (int r = 0; r < 2; r++) {
                ra[r] = *(const float4*)(Ab + (size_t)(a_row + 64 * r) * K + k0 + 16 + a_c4 * 4);
                rb[r] = *(const float4*)(Bb + (size_t)(b_row + 8 * r + k0 + 16) * N + b_c4 * 4);
            }
        }
        #pragma unroll
        for (int kk = 0; kk < 16; kk++) {
            float4 a0 = *(const float4*)&As[buf][kk][ty * 8];
            float4 a1 = *(const float4*)&As[buf][kk][ty * 8 + 4];
            float4 b0 = *(const float4*)&Bs[buf][kk][tx * 8];
            float4 b1 = *(const float4*)&Bs[buf][kk][tx * 8 + 4];
            const float rm[8] = {a0.x,a0.y,a0.z,a0.w,a1.x,a1.y,a1.z,a1.w};
            const float rn[8] = {b0.x,b0.y,b0.z,b0.w,b1.x,b1.y,b1.z,b1.w};
            #pragma unroll
            for (int i = 0; i < 8; i++)
                #pragma unroll
                for (int j = 0; j < 8; j++)
                    acc[i][j] = fmaf(rm[i], rn[j], acc[i][j]);
        }
        if (more) {
            const int nb = buf ^ 1;
            #pragma unroll
            for (int r = 0; r < 2; r++) {
                const int ar = a_row + 64 * r;
                As[nb][a_c4 * 4 + 0][ar] = ra[r].x;
                As[nb][a_c4 * 4 + 1][ar] = ra[r].y;
                As[nb][a_c4 * 4 + 2][ar] = ra[r].z;
                As[nb][a_c4 * 4 + 3][ar] = ra[r].w;
                *(float4*)&Bs[nb][b_row + 8 * r][b_c4 * 4] = rb[r];
            }
            __syncthreads();
            buf = nb;
        }
    }

    // epilogue: scatter to g_q (transposed, scaled), g_k (transposed), g_v
    #pragma unroll
    for (int i = 0; i < 8; i++) {
        const int m = by * 128 + ty * 8 + i;
        const int bb = m >> 11;
        const int n  = m & 2047;
        #pragma unroll
        for (int j = 0; j < 8; j++) {
            const int c = bx * 128 + tx * 8 + j;
            const int which = c % 3;
            const int hd = c / 3;
            const int h = hd >> 6;
            const int d = hd & 63;
            float val = acc[i][j];
            if (which == 0) {
                // q transposed [b,h,d,n], pre-scaled by 1/sqrt(64)
                g_q[(((size_t)(bb * NH + h) * DH + d) << 11) + n] = val * 0.125f;
            } else if (which == 1) {
                g_k[(((size_t)(bb * NH + h) * DH + d) << 11) + n] = val;
            } else {
                g_v[((((size_t)(bb * NH + h)) << 11) + n) * DH + d] = val;
            }
        }
    }
}

// =====================================================================
// Kernel 2: causal flash attention, 64q x 64k tiles, swizzled smem.
// All smem tiles are [64 rows][16 float4 cells], cell ^= (row>>2)&15.
// 256 threads: tx = tid&15 (4 cols each), ty = tid>>4 (4 rows each).
// =====================================================================
__global__ __launch_bounds__(256, 2) void attn_kernel()
{
    extern __shared__ __align__(16) float4 sm4[];
    float4* Qt = sm4;              // [d][q]
    float4* Kt = Qt + 64 * 16;     // [d][k]
    float4* Vt = Kt + 64 * 16;     // [k][d]
    float4* Pt = Vt + 64 * 16;     // [k][q]

    const int qt = (int)gridDim.x - 1 - (int)blockIdx.x;   // big tiles first
    const int bh = blockIdx.y;
    const int bb = bh >> 4, hh = bh & 15;
    const float* Qg = g_q + (size_t)bh * DH * NSEQ;   // [d][n]
    const float* Kg = g_k + (size_t)bh * DH * NSEQ;   // [d][n]
    const float* Vg = g_v + (size_t)bh * NSEQ * DH;   // [n][d]

    const int tid = threadIdx.x;
    const int tx = tid & 15;
    const int ty = tid >> 4;

    // load Q tile (rows d, cols q)
    #pragma unroll
    for (int r = 0; r < 4; r++) {
        const int idx = tid + 256 * r;
        const int d = idx >> 4, c4 = idx & 15;
        const float4 v = *(const float4*)(Qg + (size_t)d * NSEQ + qt * 64 + c4 * 4);
        Qt[d * 16 + (c4 ^ ((d >> 2) & 15))] = v;
    }

    float o[4][4] = {};
    float m[4], l[4];
    #pragma unroll
    for (int i = 0; i < 4; i++) { m[i] = -1e30f; l[i] = 0.f; }

    for (int kt = 0; kt <= qt; kt++) {
        __syncthreads();   // prior PV readers done (also covers Q-load on iter 0)
        // load K, V tiles
        #pragma unroll
        for (int r = 0; r < 4; r++) {
            const int idx = tid + 256 * r;
            const int row = idx >> 4, c4 = idx & 15;
            const int sw = (row >> 2) & 15;
            const float4 kv = *(const float4*)(Kg + (size_t)row * NSEQ + kt * 64 + c4 * 4);
            Kt[row * 16 + (c4 ^ sw)] = kv;
            const float4 vv = *(const float4*)(Vg + (size_t)(kt * 64 + row) * DH + c4 * 4);
            Vt[row * 16 + (c4 ^ sw)] = vv;
        }
        __syncthreads();

        // S = Q^T K  (rows q = ty*4+i, cols k = tx*4+j)
        float s[4][4] = {};
        #pragma unroll 8
        for (int kk = 0; kk < 64; kk++) {
            const int sw = (kk >> 2) & 15;
            const float4 q4 = Qt[kk * 16 + (ty ^ sw)];
            const float4 k4 = Kt[kk * 16 + (tx ^ sw)];
            const float qv[4] = {q4.x, q4.y, q4.z, q4.w};
            const float kv[4] = {k4.x, k4.y, k4.z, k4.w};
            #pragma unroll
            for (int i = 0; i < 4; i++)
                #pragma unroll
                for (int j = 0; j < 4; j++)
                    s[i][j] = fmaf(qv[i], kv[j], s[i][j]);
        }

        // online softmax (q pre-scaled by 1/sqrt(d))
        const bool diag = (kt == qt);
        #pragma unroll
        for (int i = 0; i < 4; i++) {
            if (diag) {
                const int grow = ty * 4 + i;      // local q index (same tile)
                #pragma unroll
                for (int j = 0; j < 4; j++)
                    if (tx * 4 + j > grow) s[i][j] = -1e30f;
            }
            float tm = fmaxf(fmaxf(s[i][0], s[i][1]), fmaxf(s[i][2], s[i][3]));
            #pragma unroll
            for (int off = 8; off > 0; off >>= 1)
                tm = fmaxf(tm, __shfl_xor_sync(0xffffffffu, tm, off));
            const float mnew = fmaxf(m[i], tm);
            const float f = __expf(m[i] - mnew);
            m[i] = mnew;
            float rs = 0.f;
            #pragma unroll
            for (int j = 0; j < 4; j++) {
                s[i][j] = __expf(s[i][j] - mnew);
                rs += s[i][j];
            }
            #pragma unroll
            for (int off = 8; off > 0; off >>= 1)
                rs += __shfl_xor_sync(0xffffffffu, rs, off);
            l[i] = l[i] * f + rs;
            #pragma unroll
            for (int j = 0; j < 4; j++) o[i][j] *= f;
        }

        // store P transposed: Pt[k][q], cell swizzle = ty ^ (row>>2) = ty ^ tx
        {
            const int cell = ty ^ tx;
            #pragma unroll
            for (int j = 0; j < 4; j++)
                Pt[(tx * 4 + j) * 16 + cell] = make_float4(s[0][j], s[1][j], s[2][j], s[3][j]);
        }
        __syncthreads();

        // O += P^T V (rows q = ty*4+i, d-cols tx*4+j)
        #pragma unroll 8
        for (int kk = 0; kk < 64; kk++) {
            const int sw = (kk >> 2) & 15;
            const float4 p4 = Pt[kk * 16 + (ty ^ sw)];
            const float4 v4 = Vt[kk * 16 + (tx ^ sw)];
            const float pv[4] = {p4.x, p4.y, p4.z, p4.w};
            const float vv[4] = {v4.x, v4.y, v4.z, v4.w};
            #pragma unroll
            for (int i = 0; i < 4; i++)
                #pragma unroll
                for (int j = 0; j < 4; j++)
                    o[i][j] = fmaf(pv[i], vv[j], o[i][j]);
        }
    }

    // normalize + store to g_att[b][n][h*64+d]
    #pragma unroll
    for (int i = 0; i < 4; i++) {
        const float inv = 1.f / l[i];
        const int n = qt * 64 + ty * 4 + i;
        float4 ov = make_float4(o[i][0] * inv, o[i][1] * inv, o[i][2] * inv, o[i][3] * inv);
        *(float4*)(g_att + ((size_t)bb * NSEQ + n) * DM + hh * 64 + tx * 4) = ov;
    }
}

// =====================================================================
// Kernel 3: output projection  out = g_att @ w_proj  [4096,1024]x[1024,1024]
// =====================================================================
__global__ __launch_bounds__(256, 2) void proj_gemm(const float* __restrict__ Bw,
                                                    float* __restrict__ C)
{
    constexpr int K = DM;
    constexpr int N = DM;
    __shared__ __align__(16) float As[2][16][132];
    __shared__ __align__(16) float Bs[2][16][128];

    const int bx = blockIdx.x;
    const int by = blockIdx.y;
    const int tid = threadIdx.x;
    const int tx = tid & 15;
    const int ty = tid >> 4;

    const float* Ab = g_att + (size_t)by * 128 * K;
    const float* Bb = Bw + bx * 128;

    const int a_row = tid >> 2;
    const int a_c4  = tid & 3;
    const int b_row = tid >> 5;
    const int b_c4  = tid & 31;

    float4 ra[2], rb[2];
    float acc[8][8] = {};

    #pragma unroll
    for (int r = 0; r < 2; r++) {
        ra[r] = *(const float4*)(Ab + (size_t)(a_row + 64 * r) * K + a_c4 * 4);
        rb[r] = *(const float4*)(Bb + (size_t)(b_row + 8 * r) * N + b_c4 * 4);
    }
    int buf = 0;
    #pragma unroll
    for (int r = 0; r < 2; r++) {
        const int ar = a_row + 64 * r;
        As[buf][a_c4 * 4 + 0][ar] = ra[r].x;
        As[buf][a_c4 * 4 + 1][ar] = ra[r].y;
        As[buf][a_c4 * 4 + 2][ar] = ra[r].z;
        As[buf][a_c4 * 4 + 3][ar] = ra[r].w;
        *(float4*)&Bs[buf][b_row + 8 * r][b_c4 * 4] = rb[r];
    }
    __syncthreads();

    for (int k0 = 0; k0 < K; k0 += 16) {
        const bool more = (k0 + 16 < K);
        if (more) {
            #pragma unroll
            for (int r = 0; r < 2; r++) {
                ra[r] = *(const float4*)(Ab + (size_t)(a_row + 64 * r) * K + k0 + 16 + a_c4 * 4);
                rb[r] = *(const float4*)(Bb + (size_t)(b_row + 8 * r + k0 + 16) * N + b_c4 * 4);
            }
        }
        #pragma unroll
        for (int kk = 0; kk < 16; kk++) {
            float4 a0 = *(const float4*)&As[buf][kk][ty * 8];
            float4 a1 = *(const float4*)&As[buf][kk][ty * 8 + 4];
            float4 b0 = *(const float4*)&Bs[buf][kk][tx * 8];
            float4 b1 = *(const float4*)&Bs[buf][kk][tx * 8 + 4];
            const float rm[8] = {a0.x,a0.y,a0.z,a0.w,a1.x,a1.y,a1.z,a1.w};
            const float rn[8] = {b0.x,b0.y,b0.z,b0.w,b1.x,b1.y,b1.z,b1.w};
            #pragma unroll
            for (int i = 0; i < 8; i++)
                #pragma unroll
                for (int j = 0; j < 8; j++)
                    acc[i][j] = fmaf(rm[i], rn[j], acc[i][j]);
        }
        if (more) {
            const int nb = buf ^ 1;
            #pragma unroll
            for (int r = 0; r < 2; r++) {
                const int ar = a_row + 64 * r;
                As[nb][a_c4 * 4 + 0][ar] = ra[r].x;
                As[nb][a_c4 * 4 + 1][ar] = ra[r].y;
                As[nb][a_c4 * 4 + 2][ar] = ra[r].z;
                As[nb][a_c4 * 4 + 3][ar] = ra[r].w;
                *(float4*)&Bs[nb][b_row + 8 * r][b_c4 * 4] = rb[r];
            }
            __syncthreads();
            buf = nb;
        }
    }

    #pragma unroll
    for (int i = 0; i < 8; i++) {
        const int mr = by * 128 + ty * 8 + i;
        float* cp = C + (size_t)mr * N + bx * 128 + tx * 8;
        *(float4*)(cp + 0) = make_float4(acc[i][0], acc[i][1], acc[i][2], acc[i][3]);
        *(float4*)(cp + 4) = make_float4(acc[i][4], acc[i][5], acc[i][6], acc[i][7]);
    }
}

// =====================================================================
extern "C" void kernel_launch(void* const* d_in, const int* in_sizes, int n_in,
                              void* d_out, int out_size)
{
    (void)in_sizes; (void)n_in; (void)out_size;
    const float* x      = (const float*)d_in[0];
    const float* w_qkv  = (const float*)d_in[1];
    const float* w_proj = (const float*)d_in[2];
    float* out = (float*)d_out;

    static bool attr_done = false;
    if (!attr_done) {
        cudaFuncSetAttribute(attn_kernel, cudaFuncAttributeMaxDynamicSharedMemorySize, 65536);
        attr_done = true;
    }

    qkv_gemm<<<dim3(24, 32), 256>>>(x, w_qkv);
    attn_kernel<<<dim3(32, 32), 256, 65536>>>();
    proj_gemm<<<dim3(8, 32), 256>>>(w_proj, out);
}